// round 9
// baseline (speedup 1.0000x reference)
#include <cuda_runtime.h>
#include <cuda_fp16.h>
#include <math.h>
#include <stdint.h>

#define N_NODES  100000
#define N_EDGES  1600000
#define N_GRAPHS 1000
#define D        128

// ---------------- scratch (static device globals; no allocation) ----------------
__device__ __half g_hh   [(size_t)N_NODES * D]; // current activations (fp16)
__device__ __half g_hsh  [(size_t)N_NODES * D]; // (h @ W) * dinv[row] (fp16)
__device__ __half g_Wh   [3 * D * D];           // weights, fp16, transposed [l][n][k]
__device__ float  g_dinv [N_NODES];
__device__ int    g_deg  [N_NODES];
__device__ int    g_rowptr[N_NODES + 1];
__device__ int    g_cursor[N_NODES];
__device__ int    g_esrc [N_EDGES];             // src ids sorted by dst (CSR)
__device__ float  g_gmax [N_GRAPHS * D];

// ---------------- degree count ----------------
__global__ void k_count_deg(const int* __restrict__ dst) {
    int e = blockIdx.x * blockDim.x + threadIdx.x;
    if (e < N_EDGES) atomicAdd(&g_deg[dst[e]], 1);
}

// ---------------- single-block scan: rowptr / cursor / dinv from deg ----------------
__global__ void k_scan() {
    __shared__ int ssum[1024];
    int t = threadIdx.x;
    const int CH  = (N_NODES + 1023) / 1024;
    int beg = t * CH;
    int end = min(beg + CH, N_NODES);
    int s = 0;
    for (int i = beg; i < end; i++) s += g_deg[i];
    ssum[t] = s;
    __syncthreads();
    for (int off = 1; off < 1024; off <<= 1) {
        int v = (t >= off) ? ssum[t - off] : 0;
        __syncthreads();
        ssum[t] += v;
        __syncthreads();
    }
    int run = (t > 0) ? ssum[t - 1] : 0;
    for (int i = beg; i < end; i++) {
        int dg = g_deg[i];
        g_rowptr[i] = run;
        g_cursor[i] = run;
        g_dinv[i]   = rsqrtf((float)dg + 1.0f);
        run += dg;
    }
    if (t == 0) g_rowptr[N_NODES] = N_EDGES;
}

// ---------------- CSR fill ----------------
__global__ void k_fill_csr(const int* __restrict__ src, const int* __restrict__ dst) {
    int e = blockIdx.x * blockDim.x + threadIdx.x;
    if (e >= N_EDGES) return;
    int d   = __ldg(dst + e);
    int pos = atomicAdd(&g_cursor[d], 1);
    g_esrc[pos] = __ldg(src + e);
}

// ---------------- weights -> fp16, transposed [n][k] ----------------
__global__ void k_prepW(const float* __restrict__ W0, const float* __restrict__ W1,
                        const float* __restrict__ W2) {
    int idx = blockIdx.x * blockDim.x + threadIdx.x;
    if (idx >= 3 * D * D) return;
    int l   = idx >> 14;               // D*D = 16384
    int rem = idx & (D * D - 1);
    int k   = rem >> 7;
    int n   = rem & (D - 1);
    const float* W = (l == 0) ? W0 : (l == 1) ? W1 : W2;
    g_Wh[(l << 14) + n * D + k] = __float2half_rn(W[rem]);
}

// ---------------- embedding lookup with max_norm=1 renorm -> fp16 ----------------
__global__ void k_embed(const int* __restrict__ x, const float* __restrict__ emb) {
    int t    = blockIdx.x * blockDim.x + threadIdx.x;
    int node = t >> 5;
    int lane = t & 31;
    if (node >= N_NODES) return;
    int v = __ldg(x + node);
    float4 e = __ldg((const float4*)(emb + (size_t)v * D) + lane);
    float ss = e.x * e.x + e.y * e.y + e.z * e.z + e.w * e.w;
    #pragma unroll
    for (int o = 16; o; o >>= 1) ss += __shfl_xor_sync(0xFFFFFFFFu, ss, o);
    float nrm   = sqrtf(ss);
    float scale = fminf(1.0f, 1.0f / fmaxf(nrm, 1e-7f));
    __half2 h0 = __float22half2_rn(make_float2(e.x * scale, e.y * scale));
    __half2 h1 = __float22half2_rn(make_float2(e.z * scale, e.w * scale));
    uint2 out;
    out.x = *(uint32_t*)&h0;
    out.y = *(uint32_t*)&h1;
    ((uint2*)(g_hh + (size_t)node * D))[lane] = out;
}

// ---------------- fp16 MMA helper ----------------
__device__ __forceinline__ void mma_f16(float* c, const uint32_t a0, const uint32_t a1,
                                        const uint32_t a2, const uint32_t a3,
                                        const uint32_t b0, const uint32_t b1) {
    asm volatile(
        "mma.sync.aligned.m16n8k16.row.col.f32.f16.f16.f32 "
        "{%0,%1,%2,%3}, {%4,%5,%6,%7}, {%8,%9}, {%0,%1,%2,%3};"
        : "+f"(c[0]), "+f"(c[1]), "+f"(c[2]), "+f"(c[3])
        : "r"(a0), "r"(a1), "r"(a2), "r"(a3), "r"(b0), "r"(b1));
}

// ---------------- GEMM (fp16 HMMA): hs_h = fp16((g_hh @ Wh) * dinv[row]) ----------------
// Block 128x128, 8 warps in 4(M)x2(N), warp tile 32x64, mma m16n8k16, K chunks of 32.
#define AS_STR 40     // halves; 80B row stride, conflict-free fragment loads
__global__ __launch_bounds__(256) void k_gemm(int layer) {
    __shared__ __half As [128][AS_STR];   // A tile [m][k]
    __shared__ __half BsT[128][AS_STR];   // B tile transposed [n][k]

    const __half* Wh = g_Wh + (layer << 14);

    int tid  = threadIdx.x;
    int warp = tid >> 5, lane = tid & 31;
    int g = lane >> 2, t = lane & 3;
    int wm = warp >> 1;            // 0..3
    int wn = warp & 1;             // 0..1
    int rowBase = blockIdx.x * 128;
    int mBase = wm * 32;
    int nBase = wn * 64;

    float acc[2][8][4];
    #pragma unroll
    for (int i = 0; i < 2; i++)
        #pragma unroll
        for (int j = 0; j < 8; j++)
            #pragma unroll
            for (int k = 0; k < 4; k++) acc[i][j][k] = 0.0f;

    for (int k0 = 0; k0 < D; k0 += 32) {
        // stage A: 128x32 halves = 512 uint4 (2 per thread)
        #pragma unroll
        for (int i = 0; i < 2; i++) {
            int idx = tid + i * 256;
            int r   = idx >> 2;
            int c   = (idx & 3) << 3;
            int gr  = rowBase + r;
            uint4 v = (gr < N_NODES)
                ? *(const uint4*)(g_hh + (size_t)gr * D + k0 + c)
                : make_uint4(0, 0, 0, 0);
            *(uint4*)&As[r][c] = v;
        }
        // stage B (already transposed in gmem): 128x32 halves = 512 uint4
        #pragma unroll
        for (int i = 0; i < 2; i++) {
            int idx = tid + i * 256;
            int r   = idx >> 2;        // n row
            int c   = (idx & 3) << 3;  // k col
            uint4 v = *(const uint4*)(Wh + r * D + k0 + c);
            *(uint4*)&BsT[r][c] = v;
        }
        __syncthreads();

        #pragma unroll
        for (int ks = 0; ks < 32; ks += 16) {
            uint32_t a[2][4];
            #pragma unroll
            for (int mt = 0; mt < 2; mt++) {
                int r0 = mBase + mt * 16 + g;
                int r1 = r0 + 8;
                a[mt][0] = *(const uint32_t*)&As[r0][ks + 2 * t];
                a[mt][1] = *(const uint32_t*)&As[r1][ks + 2 * t];
                a[mt][2] = *(const uint32_t*)&As[r0][ks + 2 * t + 8];
                a[mt][3] = *(const uint32_t*)&As[r1][ks + 2 * t + 8];
            }
            #pragma unroll
            for (int nt = 0; nt < 8; nt++) {
                int col = nBase + nt * 8 + g;
                uint32_t b0 = *(const uint32_t*)&BsT[col][ks + 2 * t];
                uint32_t b1 = *(const uint32_t*)&BsT[col][ks + 2 * t + 8];
                #pragma unroll
                for (int mt = 0; mt < 2; mt++)
                    mma_f16(acc[mt][nt], a[mt][0], a[mt][1], a[mt][2], a[mt][3], b0, b1);
            }
        }
        __syncthreads();
    }

    // epilogue: scale by dinv[row], convert to fp16, write hs_h
    #pragma unroll
    for (int mt = 0; mt < 2; mt++) {
        int r0 = rowBase + mBase + mt * 16 + g;
        int r1 = r0 + 8;
        float d0 = (r0 < N_NODES) ? g_dinv[r0] : 0.0f;
        float d1 = (r1 < N_NODES) ? g_dinv[r1] : 0.0f;
        #pragma unroll
        for (int nt = 0; nt < 8; nt++) {
            int col = nBase + nt * 8 + 2 * t;
            if (r0 < N_NODES) {
                __half2 hv = __float22half2_rn(
                    make_float2(acc[mt][nt][0] * d0, acc[mt][nt][1] * d0));
                *(__half2*)(g_hsh + (size_t)r0 * D + col) = hv;
            }
            if (r1 < N_NODES) {
                __half2 hv = __float22half2_rn(
                    make_float2(acc[mt][nt][2] * d1, acc[mt][nt][3] * d1));
                *(__half2*)(g_hsh + (size_t)r1 * D + col) = hv;
            }
        }
    }
}

// ---------------- fp16 row-load helper: lane covers 4 features (8 bytes) ----------------
__device__ __forceinline__ void acc_edge(float4& a, int s, int lane) {
    uint2 raw = __ldg((const uint2*)(g_hsh + (size_t)s * D) + lane);
    float2 f0 = __half22float2(*(__half2*)&raw.x);
    float2 f1 = __half22float2(*(__half2*)&raw.y);
    a.x += f0.x; a.y += f0.y; a.z += f1.x; a.w += f1.y;
}

// ---------------- CSR gather + fused epilogue (+ optional segmax), MLP=8 ----------------
template<bool LAST>
__global__ void k_gather(const float* __restrict__ b, const int* __restrict__ batch) {
    int t    = blockIdx.x * blockDim.x + threadIdx.x;
    int n    = t >> 5;
    int lane = t & 31;
    if (n >= N_NODES) return;

    int beg = __ldg(&g_rowptr[n]);
    int end = __ldg(&g_rowptr[n + 1]);

    float4 a0 = make_float4(0.f,0.f,0.f,0.f);
    float4 a1 = a0, a2 = a0, a3 = a0;

    int e = beg;
    for (; e + 8 <= end; e += 8) {
        int s[8];
        #pragma unroll
        for (int i = 0; i < 8; i++) s[i] = __ldg(&g_esrc[e + i]);
        uint2 raw[8];
        #pragma unroll
        for (int i = 0; i < 8; i++)
            raw[i] = __ldg((const uint2*)(g_hsh + (size_t)s[i] * D) + lane);
        #pragma unroll
        for (int i = 0; i < 8; i++) {
            float2 f0 = __half22float2(*(__half2*)&raw[i].x);
            float2 f1 = __half22float2(*(__half2*)&raw[i].y);
            float4& a = (i & 3) == 0 ? a0 : (i & 3) == 1 ? a1 : (i & 3) == 2 ? a2 : a3;
            a.x += f0.x; a.y += f0.y; a.z += f1.x; a.w += f1.y;
        }
    }
    for (; e + 4 <= end; e += 4) {
        int s0 = __ldg(&g_esrc[e]);
        int s1 = __ldg(&g_esrc[e + 1]);
        int s2 = __ldg(&g_esrc[e + 2]);
        int s3 = __ldg(&g_esrc[e + 3]);
        acc_edge(a0, s0, lane);
        acc_edge(a1, s1, lane);
        acc_edge(a2, s2, lane);
        acc_edge(a3, s3, lane);
    }
    for (; e < end; e++) {
        int s = __ldg(&g_esrc[e]);
        acc_edge(a0, s, lane);
    }

    // self-loop term + combine partials
    float4 self = make_float4(0.f,0.f,0.f,0.f);
    acc_edge(self, n, lane);
    float4 acc;
    acc.x = (a0.x + a1.x) + (a2.x + a3.x) + self.x;
    acc.y = (a0.y + a1.y) + (a2.y + a3.y) + self.y;
    acc.z = (a0.z + a1.z) + (a2.z + a3.z) + self.z;
    acc.w = (a0.w + a1.w) + (a2.w + a3.w) + self.w;

    float  di = g_dinv[n];
    float4 bb = __ldg((const float4*)b + lane);
    float4 o;
    o.x = fmaxf(fmaf(acc.x, di, bb.x), 0.0f);
    o.y = fmaxf(fmaf(acc.y, di, bb.y), 0.0f);
    o.z = fmaxf(fmaf(acc.z, di, bb.z), 0.0f);
    o.w = fmaxf(fmaf(acc.w, di, bb.w), 0.0f);

    if (LAST) {
        int bg = __ldg(batch + n);
        int* q = (int*)(g_gmax + (size_t)bg * D + lane * 4);
        atomicMax(q + 0, __float_as_int(o.x));
        atomicMax(q + 1, __float_as_int(o.y));
        atomicMax(q + 2, __float_as_int(o.z));
        atomicMax(q + 3, __float_as_int(o.w));
    } else {
        __half2 h0 = __float22half2_rn(make_float2(o.x, o.y));
        __half2 h1 = __float22half2_rn(make_float2(o.z, o.w));
        uint2 outv;
        outv.x = *(uint32_t*)&h0;
        outv.y = *(uint32_t*)&h1;
        ((uint2*)(g_hh + (size_t)n * D))[lane] = outv;
    }
}

// ---------------- final readout ----------------
__global__ void k_final(const float* __restrict__ Wf, const float* __restrict__ bf,
                        float* __restrict__ out) {
    int t    = blockIdx.x * blockDim.x + threadIdx.x;
    int g    = t >> 5;
    int lane = t & 31;
    if (g >= N_GRAPHS) return;
    float4 v = *((const float4*)(g_gmax + (size_t)g * D) + lane);
    float4 w = __ldg((const float4*)Wf + lane);
    float s = v.x * w.x + v.y * w.y + v.z * w.z + v.w * w.w;
    #pragma unroll
    for (int o = 16; o; o >>= 1) s += __shfl_xor_sync(0xFFFFFFFFu, s, o);
    if (lane == 0) out[g] = s + bf[0];
}

// ---------------- launch (single stream) ----------------
extern "C" void kernel_launch(void* const* d_in, const int* in_sizes, int n_in,
                              void* d_out, int out_size) {
    const int*   x     = (const int*)  d_in[0];
    const int*   ei    = (const int*)  d_in[1];
    const int*   batch = (const int*)  d_in[2];
    const float* emb   = (const float*)d_in[3];
    const float* W0    = (const float*)d_in[4];
    const float* W1    = (const float*)d_in[6];
    const float* W2    = (const float*)d_in[8];
    const float* bs[3] = {(const float*)d_in[5], (const float*)d_in[7], (const float*)d_in[9]};
    const float* Wf    = (const float*)d_in[10];
    const float* bf    = (const float*)d_in[11];
    float* out = (float*)d_out;

    const int* src = ei;
    const int* dst = ei + N_EDGES;

    void* degPtr  = nullptr; cudaGetSymbolAddress(&degPtr,  g_deg);
    void* gmaxPtr = nullptr; cudaGetSymbolAddress(&gmaxPtr, g_gmax);
    cudaMemsetAsync(degPtr,  0, (size_t)N_NODES  * sizeof(int));
    cudaMemsetAsync(gmaxPtr, 0, (size_t)N_GRAPHS * D * sizeof(float));

    k_prepW<<<(3 * D * D + 255) / 256, 256>>>(W0, W1, W2);
    k_count_deg<<<(N_EDGES + 255) / 256, 256>>>(dst);
    k_scan<<<1, 1024>>>();
    k_fill_csr<<<(N_EDGES + 255) / 256, 256>>>(src, dst);
    k_embed<<<((size_t)N_NODES * 32 + 255) / 256, 256>>>(x, emb);

    const int gatherGrid = (N_NODES * 32 + 255) / 256;
    for (int l = 0; l < 3; l++) {
        k_gemm<<<(N_NODES + 127) / 128, 256>>>(l);
        if (l < 2) k_gather<false><<<gatherGrid, 256>>>(bs[l], batch);
        else       k_gather<true ><<<gatherGrid, 256>>>(bs[l], batch);
    }

    k_final<<<(N_GRAPHS * 32 + 255) / 256, 256>>>(Wf, bf, out);
}

// round 10
// speedup vs baseline: 2.2645x; 2.2645x over previous
#include <cuda_runtime.h>
#include <cuda_fp16.h>
#include <math.h>
#include <stdint.h>

#define N_NODES  100000
#define N_EDGES  1600000
#define N_GRAPHS 1000
#define D        128
#define NBLK     98            // ceil(N_NODES / 1024)

// ---------------- scratch (static device globals; no allocation) ----------------
__device__ float  g_h    [(size_t)N_NODES * D];  // current activations (fp32)
__device__ __half g_hsh  [(size_t)N_NODES * D];  // (h @ W) * dinv[row] in fp16
__device__ float  g_dinv [N_NODES];
__device__ int    g_deg  [N_NODES];
__device__ int    g_rowptr[N_NODES + 1];
__device__ int    g_cursor[N_NODES];
__device__ int    g_esrc [N_EDGES];              // src ids sorted by dst (CSR)
__device__ int    g_bsum [NBLK];                 // per-block degree sums
__device__ int    g_bsumx[NBLK];                 // exclusive-scanned block sums
__device__ float  g_gmax [N_GRAPHS * D];

// ---------------- degree count ----------------
__global__ void k_count_deg(const int* __restrict__ dst) {
    int e = blockIdx.x * blockDim.x + threadIdx.x;
    if (e < N_EDGES) atomicAdd(&g_deg[dst[e]], 1);
}

// ---------------- coalesced CSR prefix: 3 kernels ----------------
__global__ __launch_bounds__(1024) void k_blocksum() {
    int tid = threadIdx.x;
    int i   = blockIdx.x * 1024 + tid;
    int dg  = (i < N_NODES) ? g_deg[i] : 0;
    int x = dg;
    #pragma unroll
    for (int o = 16; o; o >>= 1) x += __shfl_xor_sync(0xFFFFFFFFu, x, o);
    __shared__ int wsum[32];
    if ((tid & 31) == 0) wsum[tid >> 5] = x;
    __syncthreads();
    if (tid < 32) {
        int v = wsum[tid];
        #pragma unroll
        for (int o = 16; o; o >>= 1) v += __shfl_xor_sync(0xFFFFFFFFu, v, o);
        if (tid == 0) g_bsum[blockIdx.x] = v;
    }
}

__global__ void k_scan_part() {
    // single block of 128 threads scans NBLK partials (exclusive)
    __shared__ int s[128];
    int t = threadIdx.x;
    s[t] = (t < NBLK) ? g_bsum[t] : 0;
    __syncthreads();
    for (int off = 1; off < 128; off <<= 1) {
        int v = (t >= off) ? s[t - off] : 0;
        __syncthreads();
        s[t] += v;
        __syncthreads();
    }
    if (t < NBLK) g_bsumx[t] = s[t] - g_bsum[t];   // exclusive
}

__global__ __launch_bounds__(1024) void k_write_csr() {
    int tid  = threadIdx.x;
    int lane = tid & 31;
    int wid  = tid >> 5;
    int i    = blockIdx.x * 1024 + tid;
    int dg   = (i < N_NODES) ? g_deg[i] : 0;

    // warp inclusive scan
    int x = dg;
    #pragma unroll
    for (int o = 1; o < 32; o <<= 1) {
        int y = __shfl_up_sync(0xFFFFFFFFu, x, o);
        if (lane >= o) x += y;
    }
    __shared__ int wsum[32];
    if (lane == 31) wsum[wid] = x;
    __syncthreads();
    if (tid < 32) {
        int v = wsum[tid];
        #pragma unroll
        for (int o = 1; o < 32; o <<= 1) {
            int y = __shfl_up_sync(0xFFFFFFFFu, v, o);
            if (tid >= o) v += y;
        }
        wsum[tid] = v;
    }
    __syncthreads();

    if (i < N_NODES) {
        int base = g_bsumx[blockIdx.x] + ((wid > 0) ? wsum[wid - 1] : 0);
        int excl = base + x - dg;
        g_rowptr[i] = excl;
        g_cursor[i] = excl;
        g_dinv[i]   = rsqrtf((float)dg + 1.0f);
    }
    if (i == 0) g_rowptr[N_NODES] = N_EDGES;
}

// ---------------- CSR fill ----------------
__global__ void k_fill_csr(const int* __restrict__ src, const int* __restrict__ dst) {
    int e = blockIdx.x * blockDim.x + threadIdx.x;
    if (e >= N_EDGES) return;
    int d   = __ldg(dst + e);
    int pos = atomicAdd(&g_cursor[d], 1);
    g_esrc[pos] = __ldg(src + e);
}

// ---------------- embedding lookup with max_norm=1 renorm ----------------
__global__ void k_embed(const int* __restrict__ x, const float* __restrict__ emb) {
    int t    = blockIdx.x * blockDim.x + threadIdx.x;
    int node = t >> 5;
    int lane = t & 31;
    if (node >= N_NODES) return;
    int v = __ldg(x + node);
    float4 e = __ldg((const float4*)(emb + (size_t)v * D) + lane);
    float ss = e.x * e.x + e.y * e.y + e.z * e.z + e.w * e.w;
    #pragma unroll
    for (int o = 16; o; o >>= 1) ss += __shfl_xor_sync(0xFFFFFFFFu, ss, o);
    float nrm   = sqrtf(ss);
    float scale = fminf(1.0f, 1.0f / fmaxf(nrm, 1e-7f));
    e.x *= scale; e.y *= scale; e.z *= scale; e.w *= scale;
    ((float4*)(g_h + (size_t)node * D))[lane] = e;
}

// ---------------- TF32 helpers ----------------
__device__ __forceinline__ uint32_t f2tf32(float x) {
    uint32_t r;
    asm("cvt.rna.tf32.f32 %0, %1;" : "=r"(r) : "f"(x));
    return r;
}
__device__ __forceinline__ void mma_tf32(float* c, const uint32_t a0, const uint32_t a1,
                                         const uint32_t a2, const uint32_t a3,
                                         const uint32_t b0, const uint32_t b1) {
    asm volatile(
        "mma.sync.aligned.m16n8k8.row.col.f32.tf32.tf32.f32 "
        "{%0,%1,%2,%3}, {%4,%5,%6,%7}, {%8,%9}, {%0,%1,%2,%3};"
        : "+f"(c[0]), "+f"(c[1]), "+f"(c[2]), "+f"(c[3])
        : "r"(a0), "r"(a1), "r"(a2), "r"(a3), "r"(b0), "r"(b1));
}

// ---------------- GEMM (single TF32, staged-convert): hs_h = fp16((g_h @ W) * dinv) ----
// Block 128x128, 8 warps in 4(M)x2(N), warp tile 32x64, mma m16n8k8.
#define A_STRIDE 36
#define B_STRIDE 136
__global__ __launch_bounds__(256) void k_gemm(const float* __restrict__ W) {
    __shared__ uint32_t As[128][A_STRIDE];
    __shared__ uint32_t Bs[32][B_STRIDE];

    int tid  = threadIdx.x;
    int warp = tid >> 5, lane = tid & 31;
    int g = lane >> 2, t = lane & 3;
    int wm = warp >> 1;            // 0..3
    int wn = warp & 1;             // 0..1
    int rowBase = blockIdx.x * 128;
    int mBase = wm * 32;
    int nBase = wn * 64;

    float acc[2][8][4];
    #pragma unroll
    for (int i = 0; i < 2; i++)
        #pragma unroll
        for (int j = 0; j < 8; j++)
            #pragma unroll
            for (int k = 0; k < 4; k++) acc[i][j][k] = 0.0f;

    for (int k0 = 0; k0 < D; k0 += 32) {
        #pragma unroll
        for (int i = 0; i < 4; i++) {
            int idx = tid + i * 256;
            int r   = idx >> 3;
            int c   = (idx & 7) << 2;
            int gr  = rowBase + r;
            float4 v = (gr < N_NODES)
                ? __ldg((const float4*)(g_h + (size_t)gr * D + k0 + c))
                : make_float4(0.f, 0.f, 0.f, 0.f);
            *(uint4*)&As[r][c] = make_uint4(f2tf32(v.x), f2tf32(v.y), f2tf32(v.z), f2tf32(v.w));
        }
        #pragma unroll
        for (int i = 0; i < 4; i++) {
            int idx = tid + i * 256;
            int r   = idx >> 5;
            int c   = (idx & 31) << 2;
            float4 v = __ldg((const float4*)(W + (size_t)(k0 + r) * D + c));
            *(uint4*)&Bs[r][c] = make_uint4(f2tf32(v.x), f2tf32(v.y), f2tf32(v.z), f2tf32(v.w));
        }
        __syncthreads();

        #pragma unroll
        for (int ks = 0; ks < 32; ks += 8) {
            uint32_t a[2][4];
            #pragma unroll
            for (int mt = 0; mt < 2; mt++) {
                int r0 = mBase + mt * 16 + g;
                int r1 = r0 + 8;
                a[mt][0] = As[r0][ks + t];
                a[mt][1] = As[r1][ks + t];
                a[mt][2] = As[r0][ks + t + 4];
                a[mt][3] = As[r1][ks + t + 4];
            }
            #pragma unroll
            for (int nt = 0; nt < 8; nt++) {
                int col = nBase + nt * 8 + g;
                uint32_t b0 = Bs[ks + t][col];
                uint32_t b1 = Bs[ks + t + 4][col];
                #pragma unroll
                for (int mt = 0; mt < 2; mt++)
                    mma_tf32(acc[mt][nt], a[mt][0], a[mt][1], a[mt][2], a[mt][3], b0, b1);
            }
        }
        __syncthreads();
    }

    // epilogue: scale by dinv[row], convert to fp16, write hs_h
    #pragma unroll
    for (int mt = 0; mt < 2; mt++) {
        int r0 = rowBase + mBase + mt * 16 + g;
        int r1 = r0 + 8;
        float d0 = (r0 < N_NODES) ? g_dinv[r0] : 0.0f;
        float d1 = (r1 < N_NODES) ? g_dinv[r1] : 0.0f;
        #pragma unroll
        for (int nt = 0; nt < 8; nt++) {
            int col = nBase + nt * 8 + 2 * t;
            if (r0 < N_NODES) {
                __half2 hv = __float22half2_rn(
                    make_float2(acc[mt][nt][0] * d0, acc[mt][nt][1] * d0));
                *(__half2*)(g_hsh + (size_t)r0 * D + col) = hv;
            }
            if (r1 < N_NODES) {
                __half2 hv = __float22half2_rn(
                    make_float2(acc[mt][nt][2] * d1, acc[mt][nt][3] * d1));
                *(__half2*)(g_hsh + (size_t)r1 * D + col) = hv;
            }
        }
    }
}

// ---------------- fp16 row-load helper: lane covers 4 features (8 bytes) ----------------
__device__ __forceinline__ void acc_edge(float4& a, int s, int lane) {
    uint2 raw = __ldg((const uint2*)(g_hsh + (size_t)s * D) + lane);
    float2 f0 = __half22float2(*(__half2*)&raw.x);
    float2 f1 = __half22float2(*(__half2*)&raw.y);
    a.x += f0.x; a.y += f0.y; a.z += f1.x; a.w += f1.y;
}

// ---------------- CSR gather + fused epilogue (+ optional segmax), MLP=8 ----------------
template<bool LAST>
__global__ void k_gather(const float* __restrict__ b, const int* __restrict__ batch) {
    int t    = blockIdx.x * blockDim.x + threadIdx.x;
    int n    = t >> 5;
    int lane = t & 31;
    if (n >= N_NODES) return;

    int beg = __ldg(&g_rowptr[n]);
    int end = __ldg(&g_rowptr[n + 1]);

    float4 a0 = make_float4(0.f,0.f,0.f,0.f);
    float4 a1 = a0, a2 = a0, a3 = a0;

    int e = beg;
    for (; e + 8 <= end; e += 8) {
        int s[8];
        #pragma unroll
        for (int i = 0; i < 8; i++) s[i] = __ldg(&g_esrc[e + i]);
        uint2 raw[8];
        #pragma unroll
        for (int i = 0; i < 8; i++)
            raw[i] = __ldg((const uint2*)(g_hsh + (size_t)s[i] * D) + lane);
        #pragma unroll
        for (int i = 0; i < 8; i++) {
            float2 f0 = __half22float2(*(__half2*)&raw[i].x);
            float2 f1 = __half22float2(*(__half2*)&raw[i].y);
            float4& a = (i & 3) == 0 ? a0 : (i & 3) == 1 ? a1 : (i & 3) == 2 ? a2 : a3;
            a.x += f0.x; a.y += f0.y; a.z += f1.x; a.w += f1.y;
        }
    }
    for (; e + 4 <= end; e += 4) {
        int s0 = __ldg(&g_esrc[e]);
        int s1 = __ldg(&g_esrc[e + 1]);
        int s2 = __ldg(&g_esrc[e + 2]);
        int s3 = __ldg(&g_esrc[e + 3]);
        acc_edge(a0, s0, lane);
        acc_edge(a1, s1, lane);
        acc_edge(a2, s2, lane);
        acc_edge(a3, s3, lane);
    }
    for (; e < end; e++) {
        int s = __ldg(&g_esrc[e]);
        acc_edge(a0, s, lane);
    }

    // self-loop term + combine partials
    float4 self = make_float4(0.f,0.f,0.f,0.f);
    acc_edge(self, n, lane);
    float4 acc;
    acc.x = (a0.x + a1.x) + (a2.x + a3.x) + self.x;
    acc.y = (a0.y + a1.y) + (a2.y + a3.y) + self.y;
    acc.z = (a0.z + a1.z) + (a2.z + a3.z) + self.z;
    acc.w = (a0.w + a1.w) + (a2.w + a3.w) + self.w;

    float  di = g_dinv[n];
    float4 bb = __ldg((const float4*)b + lane);
    float4 o;
    o.x = fmaxf(fmaf(acc.x, di, bb.x), 0.0f);
    o.y = fmaxf(fmaf(acc.y, di, bb.y), 0.0f);
    o.z = fmaxf(fmaf(acc.z, di, bb.z), 0.0f);
    o.w = fmaxf(fmaf(acc.w, di, bb.w), 0.0f);

    if (LAST) {
        int bg = __ldg(batch + n);
        int* q = (int*)(g_gmax + (size_t)bg * D + lane * 4);
        atomicMax(q + 0, __float_as_int(o.x));
        atomicMax(q + 1, __float_as_int(o.y));
        atomicMax(q + 2, __float_as_int(o.z));
        atomicMax(q + 3, __float_as_int(o.w));
    } else {
        *((float4*)(g_h + (size_t)n * D) + lane) = o;
    }
}

// ---------------- final readout ----------------
__global__ void k_final(const float* __restrict__ Wf, const float* __restrict__ bf,
                        float* __restrict__ out) {
    int t    = blockIdx.x * blockDim.x + threadIdx.x;
    int g    = t >> 5;
    int lane = t & 31;
    if (g >= N_GRAPHS) return;
    float4 v = *((const float4*)(g_gmax + (size_t)g * D) + lane);
    float4 w = __ldg((const float4*)Wf + lane);
    float s = v.x * w.x + v.y * w.y + v.z * w.z + v.w * w.w;
    #pragma unroll
    for (int o = 16; o; o >>= 1) s += __shfl_xor_sync(0xFFFFFFFFu, s, o);
    if (lane == 0) out[g] = s + bf[0];
}

// ---------------- launch (single stream) ----------------
extern "C" void kernel_launch(void* const* d_in, const int* in_sizes, int n_in,
                              void* d_out, int out_size) {
    const int*   x     = (const int*)  d_in[0];
    const int*   ei    = (const int*)  d_in[1];
    const int*   batch = (const int*)  d_in[2];
    const float* emb   = (const float*)d_in[3];
    const float* Ws[3] = {(const float*)d_in[4], (const float*)d_in[6], (const float*)d_in[8]};
    const float* bs[3] = {(const float*)d_in[5], (const float*)d_in[7], (const float*)d_in[9]};
    const float* Wf    = (const float*)d_in[10];
    const float* bf    = (const float*)d_in[11];
    float* out = (float*)d_out;

    const int* src = ei;
    const int* dst = ei + N_EDGES;

    void* degPtr  = nullptr; cudaGetSymbolAddress(&degPtr,  g_deg);
    void* gmaxPtr = nullptr; cudaGetSymbolAddress(&gmaxPtr, g_gmax);
    cudaMemsetAsync(degPtr,  0, (size_t)N_NODES  * sizeof(int));
    cudaMemsetAsync(gmaxPtr, 0, (size_t)N_GRAPHS * D * sizeof(float));

    k_count_deg<<<(N_EDGES + 255) / 256, 256>>>(dst);
    k_blocksum<<<NBLK, 1024>>>();
    k_scan_part<<<1, 128>>>();
    k_write_csr<<<NBLK, 1024>>>();
    k_fill_csr<<<(N_EDGES + 255) / 256, 256>>>(src, dst);
    k_embed<<<((size_t)N_NODES * 32 + 255) / 256, 256>>>(x, emb);

    const int gatherGrid = (N_NODES * 32 + 255) / 256;
    for (int l = 0; l < 3; l++) {
        k_gemm<<<(N_NODES + 127) / 128, 256>>>(Ws[l]);
        if (l < 2) k_gather<false><<<gatherGrid, 256>>>(bs[l], batch);
        else       k_gather<true ><<<gatherGrid, 256>>>(bs[l], batch);
    }

    k_final<<<(N_GRAPHS * 32 + 255) / 256, 256>>>(Wf, bf, out);
}

// round 11
// speedup vs baseline: 2.3622x; 1.0431x over previous
#include <cuda_runtime.h>
#include <cuda_fp16.h>
#include <math.h>
#include <stdint.h>

#define N_NODES  100000
#define N_EDGES  1600000
#define N_GRAPHS 1000
#define D        128
#define NBLK     98            // ceil(N_NODES / 1024)

// ---------------- scratch (static device globals; no allocation) ----------------
__device__ __half g_hh   [(size_t)N_NODES * D];  // current activations (fp16)
__device__ __half g_hsh  [(size_t)N_NODES * D];  // (h @ W) * dinv[row] in fp16
__device__ float  g_dinv [N_NODES];
__device__ int    g_deg  [N_NODES];
__device__ int    g_rowptr[N_NODES + 1];
__device__ int    g_cursor[N_NODES];
__device__ int    g_esrc [N_EDGES];              // src ids sorted by dst (CSR)
__device__ int    g_bsum [NBLK];
__device__ int    g_bsumx[NBLK];
__device__ float  g_gmax [N_GRAPHS * D];

// ---------------- degree count ----------------
__global__ void k_count_deg(const int* __restrict__ dst) {
    int e = blockIdx.x * blockDim.x + threadIdx.x;
    if (e < N_EDGES) atomicAdd(&g_deg[dst[e]], 1);
}

// ---------------- coalesced CSR prefix: 3 kernels ----------------
__global__ __launch_bounds__(1024) void k_blocksum() {
    int tid = threadIdx.x;
    int i   = blockIdx.x * 1024 + tid;
    int dg  = (i < N_NODES) ? g_deg[i] : 0;
    int x = dg;
    #pragma unroll
    for (int o = 16; o; o >>= 1) x += __shfl_xor_sync(0xFFFFFFFFu, x, o);
    __shared__ int wsum[32];
    if ((tid & 31) == 0) wsum[tid >> 5] = x;
    __syncthreads();
    if (tid < 32) {
        int v = wsum[tid];
        #pragma unroll
        for (int o = 16; o; o >>= 1) v += __shfl_xor_sync(0xFFFFFFFFu, v, o);
        if (tid == 0) g_bsum[blockIdx.x] = v;
    }
}

__global__ void k_scan_part() {
    __shared__ int s[128];
    int t = threadIdx.x;
    s[t] = (t < NBLK) ? g_bsum[t] : 0;
    __syncthreads();
    for (int off = 1; off < 128; off <<= 1) {
        int v = (t >= off) ? s[t - off] : 0;
        __syncthreads();
        s[t] += v;
        __syncthreads();
    }
    if (t < NBLK) g_bsumx[t] = s[t] - g_bsum[t];   // exclusive
}

__global__ __launch_bounds__(1024) void k_write_csr() {
    int tid  = threadIdx.x;
    int lane = tid & 31;
    int wid  = tid >> 5;
    int i    = blockIdx.x * 1024 + tid;
    int dg   = (i < N_NODES) ? g_deg[i] : 0;

    int x = dg;
    #pragma unroll
    for (int o = 1; o < 32; o <<= 1) {
        int y = __shfl_up_sync(0xFFFFFFFFu, x, o);
        if (lane >= o) x += y;
    }
    __shared__ int wsum[32];
    if (lane == 31) wsum[wid] = x;
    __syncthreads();
    if (tid < 32) {
        int v = wsum[tid];
        #pragma unroll
        for (int o = 1; o < 32; o <<= 1) {
            int y = __shfl_up_sync(0xFFFFFFFFu, v, o);
            if (tid >= o) v += y;
        }
        wsum[tid] = v;
    }
    __syncthreads();

    if (i < N_NODES) {
        int base = g_bsumx[blockIdx.x] + ((wid > 0) ? wsum[wid - 1] : 0);
        int excl = base + x - dg;
        g_rowptr[i] = excl;
        g_cursor[i] = excl;
        g_dinv[i]   = rsqrtf((float)dg + 1.0f);
    }
    if (i == 0) g_rowptr[N_NODES] = N_EDGES;
}

// ---------------- CSR fill ----------------
__global__ void k_fill_csr(const int* __restrict__ src, const int* __restrict__ dst) {
    int e = blockIdx.x * blockDim.x + threadIdx.x;
    if (e >= N_EDGES) return;
    int d   = __ldg(dst + e);
    int pos = atomicAdd(&g_cursor[d], 1);
    g_esrc[pos] = __ldg(src + e);
}

// ---------------- embedding lookup with max_norm=1 renorm -> fp16 ----------------
__global__ void k_embed(const int* __restrict__ x, const float* __restrict__ emb) {
    int t    = blockIdx.x * blockDim.x + threadIdx.x;
    int node = t >> 5;
    int lane = t & 31;
    if (node >= N_NODES) return;
    int v = __ldg(x + node);
    float4 e = __ldg((const float4*)(emb + (size_t)v * D) + lane);
    float ss = e.x * e.x + e.y * e.y + e.z * e.z + e.w * e.w;
    #pragma unroll
    for (int o = 16; o; o >>= 1) ss += __shfl_xor_sync(0xFFFFFFFFu, ss, o);
    float nrm   = sqrtf(ss);
    float scale = fminf(1.0f, 1.0f / fmaxf(nrm, 1e-7f));
    __half2 h0 = __float22half2_rn(make_float2(e.x * scale, e.y * scale));
    __half2 h1 = __float22half2_rn(make_float2(e.z * scale, e.w * scale));
    uint2 outv;
    outv.x = *(uint32_t*)&h0;
    outv.y = *(uint32_t*)&h1;
    ((uint2*)(g_hh + (size_t)node * D))[lane] = outv;
}

// ---------------- TF32 helpers ----------------
__device__ __forceinline__ uint32_t f2tf32(float x) {
    uint32_t r;
    asm("cvt.rna.tf32.f32 %0, %1;" : "=r"(r) : "f"(x));
    return r;
}
__device__ __forceinline__ uint2 h2_to_tf32(uint32_t h2raw) {
    float2 f = __half22float2(*(__half2*)&h2raw);
    return make_uint2(f2tf32(f.x), f2tf32(f.y));
}
__device__ __forceinline__ void mma_tf32(float* c, const uint32_t a0, const uint32_t a1,
                                         const uint32_t a2, const uint32_t a3,
                                         const uint32_t b0, const uint32_t b1) {
    asm volatile(
        "mma.sync.aligned.m16n8k8.row.col.f32.tf32.tf32.f32 "
        "{%0,%1,%2,%3}, {%4,%5,%6,%7}, {%8,%9}, {%0,%1,%2,%3};"
        : "+f"(c[0]), "+f"(c[1]), "+f"(c[2]), "+f"(c[3])
        : "r"(a0), "r"(a1), "r"(a2), "r"(a3), "r"(b0), "r"(b1));
}

// ---------------- GEMM (single TF32, fp16 A input, register prefetch) ----------------
// hs_h = fp16((fp32(g_hh) @ W) * dinv[row])
// Block 128x128, 8 warps 4(M)x2(N), warp tile 32x64, mma m16n8k8, K chunks of 32.
#define A_STRIDE 36
#define B_STRIDE 136
__global__ __launch_bounds__(256) void k_gemm(const float* __restrict__ W) {
    __shared__ uint32_t As[128][A_STRIDE];
    __shared__ uint32_t Bs[32][B_STRIDE];

    int tid  = threadIdx.x;
    int warp = tid >> 5, lane = tid & 31;
    int g = lane >> 2, t = lane & 3;
    int wm = warp >> 1;            // 0..3
    int wn = warp & 1;             // 0..1
    int rowBase = blockIdx.x * 128;
    int mBase = wm * 32;
    int nBase = wn * 64;

    float acc[2][8][4];
    #pragma unroll
    for (int i = 0; i < 2; i++)
        #pragma unroll
        for (int j = 0; j < 8; j++)
            #pragma unroll
            for (int k = 0; k < 4; k++) acc[i][j][k] = 0.0f;

    // staging coords
    const int ar  = tid >> 1;              // A row (2 threads per row)
    const int ac  = (tid & 1) << 4;        // A col base: 0 or 16 (16 halves)
    const int agr = rowBase + ar;
    const bool aok = agr < N_NODES;

    uint4  aRaw[2];                        // 16 halves
    float4 bReg[4];

    // prefetch chunk 0
    {
        const __half* ap = g_hh + (size_t)agr * D + ac;
        aRaw[0] = aok ? *(const uint4*)(ap)     : make_uint4(0,0,0,0);
        aRaw[1] = aok ? *(const uint4*)(ap + 8) : make_uint4(0,0,0,0);
        #pragma unroll
        for (int i = 0; i < 4; i++) {
            int idx = tid + i * 256;
            int r   = idx >> 5;
            int c   = (idx & 31) << 2;
            bReg[i] = __ldg((const float4*)(W + (size_t)r * D + c));
        }
    }

    for (int kc = 0; kc < 4; kc++) {
        // cvt + store current chunk to smem
        #pragma unroll
        for (int h = 0; h < 2; h++) {
            uint2 p0 = h2_to_tf32(aRaw[h].x);
            uint2 p1 = h2_to_tf32(aRaw[h].y);
            uint2 p2 = h2_to_tf32(aRaw[h].z);
            uint2 p3 = h2_to_tf32(aRaw[h].w);
            int off = ac + h * 8;
            *(uint4*)&As[ar][off]     = make_uint4(p0.x, p0.y, p1.x, p1.y);
            *(uint4*)&As[ar][off + 4] = make_uint4(p2.x, p2.y, p3.x, p3.y);
        }
        #pragma unroll
        for (int i = 0; i < 4; i++) {
            int idx = tid + i * 256;
            int r   = idx >> 5;
            int c   = (idx & 31) << 2;
            *(uint4*)&Bs[r][c] = make_uint4(f2tf32(bReg[i].x), f2tf32(bReg[i].y),
                                            f2tf32(bReg[i].z), f2tf32(bReg[i].w));
        }
        __syncthreads();

        // prefetch next chunk while MMAs run
        if (kc < 3) {
            int k0 = (kc + 1) * 32;
            const __half* ap = g_hh + (size_t)agr * D + k0 + ac;
            aRaw[0] = aok ? *(const uint4*)(ap)     : make_uint4(0,0,0,0);
            aRaw[1] = aok ? *(const uint4*)(ap + 8) : make_uint4(0,0,0,0);
            #pragma unroll
            for (int i = 0; i < 4; i++) {
                int idx = tid + i * 256;
                int r   = idx >> 5;
                int c   = (idx & 31) << 2;
                bReg[i] = __ldg((const float4*)(W + (size_t)(k0 + r) * D + c));
            }
        }

        #pragma unroll
        for (int ks = 0; ks < 32; ks += 8) {
            uint32_t a[2][4];
            #pragma unroll
            for (int mt = 0; mt < 2; mt++) {
                int r0 = mBase + mt * 16 + g;
                int r1 = r0 + 8;
                a[mt][0] = As[r0][ks + t];
                a[mt][1] = As[r1][ks + t];
                a[mt][2] = As[r0][ks + t + 4];
                a[mt][3] = As[r1][ks + t + 4];
            }
            #pragma unroll
            for (int nt = 0; nt < 8; nt++) {
                int col = nBase + nt * 8 + g;
                uint32_t b0 = Bs[ks + t][col];
                uint32_t b1 = Bs[ks + t + 4][col];
                #pragma unroll
                for (int mt = 0; mt < 2; mt++)
                    mma_tf32(acc[mt][nt], a[mt][0], a[mt][1], a[mt][2], a[mt][3], b0, b1);
            }
        }
        __syncthreads();
    }

    // epilogue: scale by dinv[row], convert to fp16, write hs_h
    #pragma unroll
    for (int mt = 0; mt < 2; mt++) {
        int r0 = rowBase + mBase + mt * 16 + g;
        int r1 = r0 + 8;
        float d0 = (r0 < N_NODES) ? g_dinv[r0] : 0.0f;
        float d1 = (r1 < N_NODES) ? g_dinv[r1] : 0.0f;
        #pragma unroll
        for (int nt = 0; nt < 8; nt++) {
            int col = nBase + nt * 8 + 2 * t;
            if (r0 < N_NODES) {
                __half2 hv = __float22half2_rn(
                    make_float2(acc[mt][nt][0] * d0, acc[mt][nt][1] * d0));
                *(__half2*)(g_hsh + (size_t)r0 * D + col) = hv;
            }
            if (r1 < N_NODES) {
                __half2 hv = __float22half2_rn(
                    make_float2(acc[mt][nt][2] * d1, acc[mt][nt][3] * d1));
                *(__half2*)(g_hsh + (size_t)r1 * D + col) = hv;
            }
        }
    }
}

// ---------------- fp16 row-load helper: lane covers 4 features (8 bytes) ----------------
__device__ __forceinline__ void acc_edge(float4& a, int s, int lane) {
    uint2 raw = __ldg((const uint2*)(g_hsh + (size_t)s * D) + lane);
    float2 f0 = __half22float2(*(__half2*)&raw.x);
    float2 f1 = __half22float2(*(__half2*)&raw.y);
    a.x += f0.x; a.y += f0.y; a.z += f1.x; a.w += f1.y;
}

// ---------------- CSR gather + fused epilogue (+ optional segmax), MLP=8 ----------------
template<bool LAST>
__global__ void k_gather(const float* __restrict__ b, const int* __restrict__ batch) {
    int t    = blockIdx.x * blockDim.x + threadIdx.x;
    int n    = t >> 5;
    int lane = t & 31;
    if (n >= N_NODES) return;

    int beg = __ldg(&g_rowptr[n]);
    int end = __ldg(&g_rowptr[n + 1]);

    float4 a0 = make_float4(0.f,0.f,0.f,0.f);
    float4 a1 = a0, a2 = a0, a3 = a0;

    int e = beg;
    for (; e + 8 <= end; e += 8) {
        int s[8];
        #pragma unroll
        for (int i = 0; i < 8; i++) s[i] = __ldg(&g_esrc[e + i]);
        uint2 raw[8];
        #pragma unroll
        for (int i = 0; i < 8; i++)
            raw[i] = __ldg((const uint2*)(g_hsh + (size_t)s[i] * D) + lane);
        #pragma unroll
        for (int i = 0; i < 8; i++) {
            float2 f0 = __half22float2(*(__half2*)&raw[i].x);
            float2 f1 = __half22float2(*(__half2*)&raw[i].y);
            float4& a = (i & 3) == 0 ? a0 : (i & 3) == 1 ? a1 : (i & 3) == 2 ? a2 : a3;
            a.x += f0.x; a.y += f0.y; a.z += f1.x; a.w += f1.y;
        }
    }
    for (; e + 4 <= end; e += 4) {
        int s0 = __ldg(&g_esrc[e]);
        int s1 = __ldg(&g_esrc[e + 1]);
        int s2 = __ldg(&g_esrc[e + 2]);
        int s3 = __ldg(&g_esrc[e + 3]);
        acc_edge(a0, s0, lane);
        acc_edge(a1, s1, lane);
        acc_edge(a2, s2, lane);
        acc_edge(a3, s3, lane);
    }
    for (; e < end; e++) {
        int s = __ldg(&g_esrc[e]);
        acc_edge(a0, s, lane);
    }

    // self-loop term + combine partials
    float4 self = make_float4(0.f,0.f,0.f,0.f);
    acc_edge(self, n, lane);
    float4 acc;
    acc.x = (a0.x + a1.x) + (a2.x + a3.x) + self.x;
    acc.y = (a0.y + a1.y) + (a2.y + a3.y) + self.y;
    acc.z = (a0.z + a1.z) + (a2.z + a3.z) + self.z;
    acc.w = (a0.w + a1.w) + (a2.w + a3.w) + self.w;

    float  di = g_dinv[n];
    float4 bb = __ldg((const float4*)b + lane);
    float4 o;
    o.x = fmaxf(fmaf(acc.x, di, bb.x), 0.0f);
    o.y = fmaxf(fmaf(acc.y, di, bb.y), 0.0f);
    o.z = fmaxf(fmaf(acc.z, di, bb.z), 0.0f);
    o.w = fmaxf(fmaf(acc.w, di, bb.w), 0.0f);

    if (LAST) {
        int bg = __ldg(batch + n);
        int* q = (int*)(g_gmax + (size_t)bg * D + lane * 4);
        atomicMax(q + 0, __float_as_int(o.x));
        atomicMax(q + 1, __float_as_int(o.y));
        atomicMax(q + 2, __float_as_int(o.z));
        atomicMax(q + 3, __float_as_int(o.w));
    } else {
        __half2 h0 = __float22half2_rn(make_float2(o.x, o.y));
        __half2 h1 = __float22half2_rn(make_float2(o.z, o.w));
        uint2 outv;
        outv.x = *(uint32_t*)&h0;
        outv.y = *(uint32_t*)&h1;
        ((uint2*)(g_hh + (size_t)n * D))[lane] = outv;
    }
}

// ---------------- final readout ----------------
__global__ void k_final(const float* __restrict__ Wf, const float* __restrict__ bf,
                        float* __restrict__ out) {
    int t    = blockIdx.x * blockDim.x + threadIdx.x;
    int g    = t >> 5;
    int lane = t & 31;
    if (g >= N_GRAPHS) return;
    float4 v = *((const float4*)(g_gmax + (size_t)g * D) + lane);
    float4 w = __ldg((const float4*)Wf + lane);
    float s = v.x * w.x + v.y * w.y + v.z * w.z + v.w * w.w;
    #pragma unroll
    for (int o = 16; o; o >>= 1) s += __shfl_xor_sync(0xFFFFFFFFu, s, o);
    if (lane == 0) out[g] = s + bf[0];
}

// ---------------- launch (single stream) ----------------
extern "C" void kernel_launch(void* const* d_in, const int* in_sizes, int n_in,
                              void* d_out, int out_size) {
    const int*   x     = (const int*)  d_in[0];
    const int*   ei    = (const int*)  d_in[1];
    const int*   batch = (const int*)  d_in[2];
    const float* emb   = (const float*)d_in[3];
    const float* Ws[3] = {(const float*)d_in[4], (const float*)d_in[6], (const float*)d_in[8]};
    const float* bs[3] = {(const float*)d_in[5], (const float*)d_in[7], (const float*)d_in[9]};
    const float* Wf    = (const float*)d_in[10];
    const float* bf    = (const float*)d_in[11];
    float* out = (float*)d_out;

    const int* src = ei;
    const int* dst = ei + N_EDGES;

    void* degPtr  = nullptr; cudaGetSymbolAddress(&degPtr,  g_deg);
    void* gmaxPtr = nullptr; cudaGetSymbolAddress(&gmaxPtr, g_gmax);
    cudaMemsetAsync(degPtr,  0, (size_t)N_NODES  * sizeof(int));
    cudaMemsetAsync(gmaxPtr, 0, (size_t)N_GRAPHS * D * sizeof(float));

    k_count_deg<<<(N_EDGES + 255) / 256, 256>>>(dst);
    k_blocksum<<<NBLK, 1024>>>();
    k_scan_part<<<1, 128>>>();
    k_write_csr<<<NBLK, 1024>>>();
    k_fill_csr<<<(N_EDGES + 255) / 256, 256>>>(src, dst);
    k_embed<<<((size_t)N_NODES * 32 + 255) / 256, 256>>>(x, emb);

    const int gatherGrid = (N_NODES * 32 + 255) / 256;
    for (int l = 0; l < 3; l++) {
        k_gemm<<<(N_NODES + 127) / 128, 256>>>(Ws[l]);
        if (l < 2) k_gather<false><<<gatherGrid, 256>>>(bs[l], batch);
        else       k_gather<true ><<<gatherGrid, 256>>>(bs[l], batch);
    }

    k_final<<<(N_GRAPHS * 32 + 255) / 256, 256>>>(Wf, bf, out);
}

// round 14
// speedup vs baseline: 2.4281x; 1.0279x over previous
#include <cuda_runtime.h>
#include <cuda_fp16.h>
#include <math.h>
#include <stdint.h>

#define N_NODES  100000
#define N_EDGES  1600000
#define N_GRAPHS 1000
#define D        128
#define NBLK     98            // ceil(N_NODES / 1024)

// ---------------- scratch (static device globals; no allocation) ----------------
__device__ __half g_hh   [(size_t)N_NODES * D];  // current activations (fp16)
__device__ __half g_hsh  [(size_t)N_NODES * D];  // (h @ W) * dinv[row] in fp16
__device__ float  g_dinv [N_NODES];
__device__ int    g_deg  [N_NODES];
__device__ int    g_rowptr[N_NODES + 1];
__device__ int    g_cursor[N_NODES];
__device__ int    g_esrc [N_EDGES];              // src ids sorted by dst (CSR)
__device__ int    g_bsum [NBLK];
__device__ int    g_bsumx[NBLK];
__device__ float  g_gmax [N_GRAPHS * D];

// ---------------- degree count ----------------
__global__ void k_count_deg(const int* __restrict__ dst) {
    int e = blockIdx.x * blockDim.x + threadIdx.x;
    if (e < N_EDGES) atomicAdd(&g_deg[dst[e]], 1);
}

// ---------------- coalesced CSR prefix: 3 kernels ----------------
__global__ __launch_bounds__(1024) void k_blocksum() {
    int tid = threadIdx.x;
    int i   = blockIdx.x * 1024 + tid;
    int dg  = (i < N_NODES) ? g_deg[i] : 0;
    int x = dg;
    #pragma unroll
    for (int o = 16; o; o >>= 1) x += __shfl_xor_sync(0xFFFFFFFFu, x, o);
    __shared__ int wsum[32];
    if ((tid & 31) == 0) wsum[tid >> 5] = x;
    __syncthreads();
    if (tid < 32) {
        int v = wsum[tid];
        #pragma unroll
        for (int o = 16; o; o >>= 1) v += __shfl_xor_sync(0xFFFFFFFFu, v, o);
        if (tid == 0) g_bsum[blockIdx.x] = v;
    }
}

__global__ void k_scan_part() {
    __shared__ int s[128];
    int t = threadIdx.x;
    s[t] = (t < NBLK) ? g_bsum[t] : 0;
    __syncthreads();
    for (int off = 1; off < 128; off <<= 1) {
        int v = (t >= off) ? s[t - off] : 0;
        __syncthreads();
        s[t] += v;
        __syncthreads();
    }
    if (t < NBLK) g_bsumx[t] = s[t] - g_bsum[t];   // exclusive
}

__global__ __launch_bounds__(1024) void k_write_csr() {
    int tid  = threadIdx.x;
    int lane = tid & 31;
    int wid  = tid >> 5;
    int i    = blockIdx.x * 1024 + tid;
    int dg   = (i < N_NODES) ? g_deg[i] : 0;

    int x = dg;
    #pragma unroll
    for (int o = 1; o < 32; o <<= 1) {
        int y = __shfl_up_sync(0xFFFFFFFFu, x, o);
        if (lane >= o) x += y;
    }
    __shared__ int wsum[32];
    if (lane == 31) wsum[wid] = x;
    __syncthreads();
    if (tid < 32) {
        int v = wsum[tid];
        #pragma unroll
        for (int o = 1; o < 32; o <<= 1) {
            int y = __shfl_up_sync(0xFFFFFFFFu, v, o);
            if (tid >= o) v += y;
        }
        wsum[tid] = v;
    }
    __syncthreads();

    if (i < N_NODES) {
        int base = g_bsumx[blockIdx.x] + ((wid > 0) ? wsum[wid - 1] : 0);
        int excl = base + x - dg;
        g_rowptr[i] = excl;
        g_cursor[i] = excl;
        g_dinv[i]   = rsqrtf((float)dg + 1.0f);
    }
    if (i == 0) g_rowptr[N_NODES] = N_EDGES;
}

// ---------------- CSR fill ----------------
__global__ void k_fill_csr(const int* __restrict__ src, const int* __restrict__ dst) {
    int e = blockIdx.x * blockDim.x + threadIdx.x;
    if (e >= N_EDGES) return;
    int d   = __ldg(dst + e);
    int pos = atomicAdd(&g_cursor[d], 1);
    g_esrc[pos] = __ldg(src + e);
}

// ---------------- embedding lookup with max_norm=1 renorm -> fp16 ----------------
__global__ void k_embed(const int* __restrict__ x, const float* __restrict__ emb) {
    int t    = blockIdx.x * blockDim.x + threadIdx.x;
    int node = t >> 5;
    int lane = t & 31;
    if (node >= N_NODES) return;
    int v = __ldg(x + node);
    float4 e = __ldg((const float4*)(emb + (size_t)v * D) + lane);
    float ss = e.x * e.x + e.y * e.y + e.z * e.z + e.w * e.w;
    #pragma unroll
    for (int o = 16; o; o >>= 1) ss += __shfl_xor_sync(0xFFFFFFFFu, ss, o);
    float nrm   = sqrtf(ss);
    float scale = fminf(1.0f, 1.0f / fmaxf(nrm, 1e-7f));
    __half2 h0 = __float22half2_rn(make_float2(e.x * scale, e.y * scale));
    __half2 h1 = __float22half2_rn(make_float2(e.z * scale, e.w * scale));
    uint2 outv;
    outv.x = *(uint32_t*)&h0;
    outv.y = *(uint32_t*)&h1;
    ((uint2*)(g_hh + (size_t)node * D))[lane] = outv;
}

// ---------------- TF32 helpers ----------------
__device__ __forceinline__ uint32_t f2tf32(float x) {
    uint32_t r;
    asm("cvt.rna.tf32.f32 %0, %1;" : "=r"(r) : "f"(x));
    return r;
}
__device__ __forceinline__ uint2 h2_to_tf32(uint32_t h2raw) {
    float2 f = __half22float2(*(__half2*)&h2raw);
    return make_uint2(f2tf32(f.x), f2tf32(f.y));
}
__device__ __forceinline__ void mma_tf32(float* c, const uint32_t a0, const uint32_t a1,
                                         const uint32_t a2, const uint32_t a3,
                                         const uint32_t b0, const uint32_t b1) {
    asm volatile(
        "mma.sync.aligned.m16n8k8.row.col.f32.tf32.tf32.f32 "
        "{%0,%1,%2,%3}, {%4,%5,%6,%7}, {%8,%9}, {%0,%1,%2,%3};"
        : "+f"(c[0]), "+f"(c[1]), "+f"(c[2]), "+f"(c[3])
        : "r"(a0), "r"(a1), "r"(a2), "r"(a3), "r"(b0), "r"(b1));
}

// ---------------- GEMM (single TF32, fp16 A input, register prefetch) ----------------
// hs_h = fp16((fp32(g_hh) @ W) * dinv[row])
// Block 128x128, 8 warps 4(M)x2(N), warp tile 32x64, mma m16n8k8, K chunks of 32.
#define A_STRIDE 36
#define B_STRIDE 136
__global__ __launch_bounds__(256) void k_gemm(const float* __restrict__ W) {
    __shared__ uint32_t As[128][A_STRIDE];
    __shared__ uint32_t Bs[32][B_STRIDE];

    int tid  = threadIdx.x;
    int warp = tid >> 5, lane = tid & 31;
    int g = lane >> 2, t = lane & 3;
    int wm = warp >> 1;            // 0..3
    int wn = warp & 1;             // 0..1
    int rowBase = blockIdx.x * 128;
    int mBase = wm * 32;
    int nBase = wn * 64;

    float acc[2][8][4];
    #pragma unroll
    for (int i = 0; i < 2; i++)
        #pragma unroll
        for (int j = 0; j < 8; j++)
            #pragma unroll
            for (int k = 0; k < 4; k++) acc[i][j][k] = 0.0f;

    // staging coords
    const int ar  = tid >> 1;              // A row (2 threads per row)
    const int ac  = (tid & 1) << 4;        // A col base: 0 or 16 (16 halves)
    const int agr = rowBase + ar;
    const bool aok = agr < N_NODES;

    uint4  aRaw[2];                        // 16 halves
    float4 bReg[4];

    // prefetch chunk 0
    {
        const __half* ap = g_hh + (size_t)agr * D + ac;
        aRaw[0] = aok ? *(const uint4*)(ap)     : make_uint4(0,0,0,0);
        aRaw[1] = aok ? *(const uint4*)(ap + 8) : make_uint4(0,0,0,0);
        #pragma unroll
        for (int i = 0; i < 4; i++) {
            int idx = tid + i * 256;
            int r   = idx >> 5;
            int c   = (idx & 31) << 2;
            bReg[i] = __ldg((const float4*)(W + (size_t)r * D + c));
        }
    }

    for (int kc = 0; kc < 4; kc++) {
        // cvt + store current chunk to smem
        #pragma unroll
        for (int h = 0; h < 2; h++) {
            uint2 p0 = h2_to_tf32(aRaw[h].x);
            uint2 p1 = h2_to_tf32(aRaw[h].y);
            uint2 p2 = h2_to_tf32(aRaw[h].z);
            uint2 p3 = h2_to_tf32(aRaw[h].w);
            int off = ac + h * 8;
            *(uint4*)&As[ar][off]     = make_uint4(p0.x, p0.y, p1.x, p1.y);
            *(uint4*)&As[ar][off + 4] = make_uint4(p2.x, p2.y, p3.x, p3.y);
        }
        #pragma unroll
        for (int i = 0; i < 4; i++) {
            int idx = tid + i * 256;
            int r   = idx >> 5;
            int c   = (idx & 31) << 2;
            *(uint4*)&Bs[r][c] = make_uint4(f2tf32(bReg[i].x), f2tf32(bReg[i].y),
                                            f2tf32(bReg[i].z), f2tf32(bReg[i].w));
        }
        __syncthreads();

        // prefetch next chunk while MMAs run
        if (kc < 3) {
            int k0 = (kc + 1) * 32;
            const __half* ap = g_hh + (size_t)agr * D + k0 + ac;
            aRaw[0] = aok ? *(const uint4*)(ap)     : make_uint4(0,0,0,0);
            aRaw[1] = aok ? *(const uint4*)(ap + 8) : make_uint4(0,0,0,0);
            #pragma unroll
            for (int i = 0; i < 4; i++) {
                int idx = tid + i * 256;
                int r   = idx >> 5;
                int c   = (idx & 31) << 2;
                bReg[i] = __ldg((const float4*)(W + (size_t)(k0 + r) * D + c));
            }
        }

        #pragma unroll
        for (int ks = 0; ks < 32; ks += 8) {
            uint32_t a[2][4];
            #pragma unroll
            for (int mt = 0; mt < 2; mt++) {
                int r0 = mBase + mt * 16 + g;
                int r1 = r0 + 8;
                a[mt][0] = As[r0][ks + t];
                a[mt][1] = As[r1][ks + t];
                a[mt][2] = As[r0][ks + t + 4];
                a[mt][3] = As[r1][ks + t + 4];
            }
            #pragma unroll
            for (int nt = 0; nt < 8; nt++) {
                int col = nBase + nt * 8 + g;
                uint32_t b0 = Bs[ks + t][col];
                uint32_t b1 = Bs[ks + t + 4][col];
                #pragma unroll
                for (int mt = 0; mt < 2; mt++)
                    mma_tf32(acc[mt][nt], a[mt][0], a[mt][1], a[mt][2], a[mt][3], b0, b1);
            }
        }
        __syncthreads();
    }

    // epilogue: scale by dinv[row], convert to fp16, write hs_h
    #pragma unroll
    for (int mt = 0; mt < 2; mt++) {
        int r0 = rowBase + mBase + mt * 16 + g;
        int r1 = r0 + 8;
        float d0 = (r0 < N_NODES) ? g_dinv[r0] : 0.0f;
        float d1 = (r1 < N_NODES) ? g_dinv[r1] : 0.0f;
        #pragma unroll
        for (int nt = 0; nt < 8; nt++) {
            int col = nBase + nt * 8 + 2 * t;
            if (r0 < N_NODES) {
                __half2 hv = __float22half2_rn(
                    make_float2(acc[mt][nt][0] * d0, acc[mt][nt][1] * d0));
                *(__half2*)(g_hsh + (size_t)r0 * D + col) = hv;
            }
            if (r1 < N_NODES) {
                __half2 hv = __float22half2_rn(
                    make_float2(acc[mt][nt][2] * d1, acc[mt][nt][3] * d1));
                *(__half2*)(g_hsh + (size_t)r1 * D + col) = hv;
            }
        }
    }
}

// ---------------- fp16 row-load helper: lane covers 4 features (8 bytes) ----------------
__device__ __forceinline__ void acc_edge(float4& a, int s, int lane) {
    uint2 raw = __ldg((const uint2*)(g_hsh + (size_t)s * D) + lane);
    float2 f0 = __half22float2(*(__half2*)&raw.x);
    float2 f1 = __half22float2(*(__half2*)&raw.y);
    a.x += f0.x; a.y += f0.y; a.z += f1.x; a.w += f1.y;
}

// ---------------- CSR gather + fused epilogue (+ optional segmax), MLP=8 ----------------
template<bool LAST>
__global__ void k_gather(const float* __restrict__ b, const int* __restrict__ batch) {
    int t    = blockIdx.x * blockDim.x + threadIdx.x;
    int n    = t >> 5;
    int lane = t & 31;
    if (n >= N_NODES) return;

    int beg = __ldg(&g_rowptr[n]);
    int end = __ldg(&g_rowptr[n + 1]);

    float4 a0 = make_float4(0.f,0.f,0.f,0.f);
    float4 a1 = a0, a2 = a0, a3 = a0;

    int e = beg;
    for (; e + 8 <= end; e += 8) {
        int s[8];
        #pragma unroll
        for (int i = 0; i < 8; i++) s[i] = __ldg(&g_esrc[e + i]);
        uint2 raw[8];
        #pragma unroll
        for (int i = 0; i < 8; i++)
            raw[i] = __ldg((const uint2*)(g_hsh + (size_t)s[i] * D) + lane);
        #pragma unroll
        for (int i = 0; i < 8; i++) {
            float2 f0 = __half22float2(*(__half2*)&raw[i].x);
            float2 f1 = __half22float2(*(__half2*)&raw[i].y);
            float4& a = (i & 3) == 0 ? a0 : (i & 3) == 1 ? a1 : (i & 3) == 2 ? a2 : a3;
            a.x += f0.x; a.y += f0.y; a.z += f1.x; a.w += f1.y;
        }
    }
    for (; e + 4 <= end; e += 4) {
        int s0 = __ldg(&g_esrc[e]);
        int s1 = __ldg(&g_esrc[e + 1]);
        int s2 = __ldg(&g_esrc[e + 2]);
        int s3 = __ldg(&g_esrc[e + 3]);
        acc_edge(a0, s0, lane);
        acc_edge(a1, s1, lane);
        acc_edge(a2, s2, lane);
        acc_edge(a3, s3, lane);
    }
    for (; e < end; e++) {
        int s = __ldg(&g_esrc[e]);
        acc_edge(a0, s, lane);
    }

    // self-loop term + combine partials
    float4 self = make_float4(0.f,0.f,0.f,0.f);
    acc_edge(self, n, lane);
    float4 acc;
    acc.x = (a0.x + a1.x) + (a2.x + a3.x) + self.x;
    acc.y = (a0.y + a1.y) + (a2.y + a3.y) + self.y;
    acc.z = (a0.z + a1.z) + (a2.z + a3.z) + self.z;
    acc.w = (a0.w + a1.w) + (a2.w + a3.w) + self.w;

    float  di = g_dinv[n];
    float4 bb = __ldg((const float4*)b + lane);
    float4 o;
    o.x = fmaxf(fmaf(acc.x, di, bb.x), 0.0f);
    o.y = fmaxf(fmaf(acc.y, di, bb.y), 0.0f);
    o.z = fmaxf(fmaf(acc.z, di, bb.z), 0.0f);
    o.w = fmaxf(fmaf(acc.w, di, bb.w), 0.0f);

    if (LAST) {
        int bg = __ldg(batch + n);
        int* q = (int*)(g_gmax + (size_t)bg * D + lane * 4);
        atomicMax(q + 0, __float_as_int(o.x));
        atomicMax(q + 1, __float_as_int(o.y));
        atomicMax(q + 2, __float_as_int(o.z));
        atomicMax(q + 3, __float_as_int(o.w));
    } else {
        __half2 h0 = __float22half2_rn(make_float2(o.x, o.y));
        __half2 h1 = __float22half2_rn(make_float2(o.z, o.w));
        uint2 outv;
        outv.x = *(uint32_t*)&h0;
        outv.y = *(uint32_t*)&h1;
        ((uint2*)(g_hh + (size_t)n * D))[lane] = outv;
    }
}

// ---------------- final readout ----------------
__global__ void k_final(const float* __restrict__ Wf, const float* __restrict__ bf,
                        float* __restrict__ out) {
    int t    = blockIdx.x * blockDim.x + threadIdx.x;
    int g    = t >> 5;
    int lane = t & 31;
    if (g >= N_GRAPHS) return;
    float4 v = *((const float4*)(g_gmax + (size_t)g * D) + lane);
    float4 w = __ldg((const float4*)Wf + lane);
    float s = v.x * w.x + v.y * w.y + v.z * w.z + v.w * w.w;
    #pragma unroll
    for (int o = 16; o; o >>= 1) s += __shfl_xor_sync(0xFFFFFFFFu, s, o);
    if (lane == 0) out[g] = s + bf[0];
}

// ---------------- launch: CSR build forked onto a side stream ----------------
extern "C" void kernel_launch(void* const* d_in, const int* in_sizes, int n_in,
                              void* d_out, int out_size) {
    const int*   x     = (const int*)  d_in[0];
    const int*   ei    = (const int*)  d_in[1];
    const int*   batch = (const int*)  d_in[2];
    const float* emb   = (const float*)d_in[3];
    const float* Ws[3] = {(const float*)d_in[4], (const float*)d_in[6], (const float*)d_in[8]};
    const float* bs[3] = {(const float*)d_in[5], (const float*)d_in[7], (const float*)d_in[9]};
    const float* Wf    = (const float*)d_in[10];
    const float* bf    = (const float*)d_in[11];
    float* out = (float*)d_out;

    const int* src = ei;
    const int* dst = ei + N_EDGES;

    // persistent side stream + events (created once, before any capture)
    static cudaStream_t s2 = [] {
        cudaStream_t s; cudaStreamCreateWithFlags(&s, cudaStreamNonBlocking); return s;
    }();
    static cudaEvent_t evFork = [] {
        cudaEvent_t e; cudaEventCreateWithFlags(&e, cudaEventDisableTiming); return e;
    }();
    static cudaEvent_t evDinv = [] {
        cudaEvent_t e; cudaEventCreateWithFlags(&e, cudaEventDisableTiming); return e;
    }();
    static cudaEvent_t evCsr = [] {
        cudaEvent_t e; cudaEventCreateWithFlags(&e, cudaEventDisableTiming); return e;
    }();

    void* degPtr  = nullptr; cudaGetSymbolAddress(&degPtr,  g_deg);
    void* gmaxPtr = nullptr; cudaGetSymbolAddress(&gmaxPtr, g_gmax);

    // fork side stream off the main (capture) stream
    cudaEventRecord(evFork, 0);
    cudaStreamWaitEvent(s2, evFork, 0);

    // side stream: CSR build chain
    cudaMemsetAsync(degPtr, 0, (size_t)N_NODES * sizeof(int), s2);
    k_count_deg<<<(N_EDGES + 255) / 256, 256, 0, s2>>>(dst);
    k_blocksum<<<NBLK, 1024, 0, s2>>>();
    k_scan_part<<<1, 128, 0, s2>>>();
    k_write_csr<<<NBLK, 1024, 0, s2>>>();
    cudaEventRecord(evDinv, s2);                 // dinv + rowptr + cursor ready
    k_fill_csr<<<(N_EDGES + 255) / 256, 256, 0, s2>>>(src, dst);
    cudaEventRecord(evCsr, s2);                  // esrc ready

    // main stream: gmax clear + embedding (independent of CSR)
    cudaMemsetAsync(gmaxPtr, 0, (size_t)N_GRAPHS * D * sizeof(float));
    k_embed<<<((size_t)N_NODES * 32 + 255) / 256, 256>>>(x, emb);

    const int gatherGrid = (N_NODES * 32 + 255) / 256;
    cudaStreamWaitEvent(0, evDinv, 0);           // gemm epilogue needs dinv
    for (int l = 0; l < 3; l++) {
        k_gemm<<<(N_NODES + 127) / 128, 256>>>(Ws[l]);
        if (l == 0) cudaStreamWaitEvent(0, evCsr, 0);   // gather needs CSR
        if (l < 2) k_gather<false><<<gatherGrid, 256>>>(bs[l], batch);
        else       k_gather<true ><<<gatherGrid, 256>>>(bs[l], batch);
    }

    k_final<<<(N_GRAPHS * 32 + 255) / 256, 256>>>(Wf, bf, out);
}